// round 3
// baseline (speedup 1.0000x reference)
#include <cuda_runtime.h>

// out[r,c] = x[r,c] * scale[c],  scale[c] = (u[c] >= 0.1f) ? vec[c]/0.9f : 0
// x: [131072, 1024] fp32. Pure HBM stream: 512 MB read + 512 MB write.

#define DEPTH 1024
#define P_DROP 0.1f

__device__ float g_scale[DEPTH];

__global__ void compute_scale_kernel(const float* __restrict__ vec,
                                     const float* __restrict__ u) {
    int c = blockIdx.x * blockDim.x + threadIdx.x;
    if (c < DEPTH) {
        float keep = (u[c] >= P_DROP) ? 1.0f : 0.0f;
        g_scale[c] = keep * vec[c] * (1.0f / (1.0f - P_DROP));
    }
}

// Each thread handles 4 float4 elements at stride S = gridDim*blockDim.
// S is a multiple of DEPTH/4 (=256), so all 4 elements share the same column
// index -> one scale load per thread. Loads batched for MLP=4; streaming
// cache hints since data is touched exactly once.
__global__ void __launch_bounds__(256)
scale_cols_kernel(const float4* __restrict__ x,
                  float4* __restrict__ out,
                  int n4) {
    const float4* __restrict__ s4 = reinterpret_cast<const float4*>(g_scale);
    int i = blockIdx.x * blockDim.x + threadIdx.x;
    int S = gridDim.x * blockDim.x;   // multiple of 256 by construction

    float4 s = __ldg(&s4[i & (DEPTH / 4 - 1)]);

    if (i + 3 * S < n4) {
        // fast path: exact fit, 4 independent streaming loads up front
        float4 a0 = __ldcs(&x[i]);
        float4 a1 = __ldcs(&x[i + S]);
        float4 a2 = __ldcs(&x[i + 2 * S]);
        float4 a3 = __ldcs(&x[i + 3 * S]);
        a0.x *= s.x; a0.y *= s.y; a0.z *= s.z; a0.w *= s.w;
        a1.x *= s.x; a1.y *= s.y; a1.z *= s.z; a1.w *= s.w;
        a2.x *= s.x; a2.y *= s.y; a2.z *= s.z; a2.w *= s.w;
        a3.x *= s.x; a3.y *= s.y; a3.z *= s.z; a3.w *= s.w;
        __stcs(&out[i],         a0);
        __stcs(&out[i + S],     a1);
        __stcs(&out[i + 2 * S], a2);
        __stcs(&out[i + 3 * S], a3);
    } else {
        // generic tail (not taken with the exact-fit grid below, kept for safety)
        for (; i < n4; i += S) {
            float4 v = __ldcs(&x[i]);
            v.x *= s.x; v.y *= s.y; v.z *= s.z; v.w *= s.w;
            __stcs(&out[i], v);
        }
    }
}

extern "C" void kernel_launch(void* const* d_in, const int* in_sizes, int n_in,
                              void* d_out, int out_size) {
    const float* x   = (const float*)d_in[0];
    const float* vec = (const float*)d_in[1];
    const float* u   = (const float*)d_in[2];
    float* out = (float*)d_out;

    compute_scale_kernel<<<(DEPTH + 255) / 256, 256>>>(vec, u);

    int n4 = out_size / 4;             // 33,554,432
    int threads = 256;
    int blocks = 32768;                // 32768*256*4 == n4 exactly
    scale_cols_kernel<<<blocks, threads>>>((const float4*)x, (float4*)out, n4);
}

// round 6
// speedup vs baseline: 1.0020x; 1.0020x over previous
#include <cuda_runtime.h>

// out[r,c] = x[r,c] * scale[c],  scale[c] = (u[c] >= 0.1f) ? vec[c]/0.9f : 0
// x: [131072, 1024] fp32. Pure HBM stream: 512 MB read + 512 MB write.
// Single fused kernel: each thread owns one column-quad (since the grid
// stride is a multiple of DEPTH/4), computes its scale float4 inline from
// vec/u (8 KB footprint, L1/L2 resident), then streams x -> out.

#define DEPTH 1024
#define P_DROP 0.1f

__global__ void __launch_bounds__(256)
fused_scale_cols_kernel(const float4* __restrict__ x,
                        const float4* __restrict__ vec4,
                        const float4* __restrict__ u4,
                        float4* __restrict__ out,
                        int n4) {
    int i = blockIdx.x * blockDim.x + threadIdx.x;
    int S = gridDim.x * blockDim.x;      // 16,777,216: multiple of 256

    // Column-quad index is invariant across grid-stride iterations.
    int c4 = i & (DEPTH / 4 - 1);
    float4 vv = __ldg(&vec4[c4]);
    float4 uu = __ldg(&u4[c4]);
    const float r = 1.0f / (1.0f - P_DROP);
    float4 s;
    s.x = (uu.x >= P_DROP) ? vv.x * r : 0.0f;
    s.y = (uu.y >= P_DROP) ? vv.y * r : 0.0f;
    s.z = (uu.z >= P_DROP) ? vv.z * r : 0.0f;
    s.w = (uu.w >= P_DROP) ? vv.w * r : 0.0f;

    for (; i < n4; i += S) {
        float4 v = x[i];
        v.x *= s.x;
        v.y *= s.y;
        v.z *= s.z;
        v.w *= s.w;
        out[i] = v;
    }
}

extern "C" void kernel_launch(void* const* d_in, const int* in_sizes, int n_in,
                              void* d_out, int out_size) {
    const float* x   = (const float*)d_in[0];
    const float* vec = (const float*)d_in[1];
    const float* u   = (const float*)d_in[2];
    float* out = (float*)d_out;

    int n4 = out_size / 4;               // 33,554,432 float4 elements
    int threads = 256;
    int blocks = 65536;                  // grid-stride: 2 iterations/thread
    fused_scale_cols_kernel<<<blocks, threads>>>(
        (const float4*)x, (const float4*)vec, (const float4*)u,
        (float4*)out, n4);
}